// round 13
// baseline (speedup 1.0000x reference)
#include <cuda_runtime.h>

#define BB 8
#define GG 64
#define PP 32768
#define NC 80
#define NCHUNK 128           // pred chunks per batch (256 preds each)

// per-(batch, chunk) partial argmax keys: (q_bits << 32) | (0xFFFFFFFF - p)
// all scratch fully overwritten every run -> no init needed, graph-safe.
__device__ unsigned long long g_partial[BB * NCHUNK * GG];
__device__ unsigned long long g_final[BB * GG];

// Kernel A: one pass over all (g, p) pairs of this block's 256 preds, writing
// FINAL outputs for every pred assuming no best-pair term (the <=384 preds
// that carry one are patched by patch_kernel afterwards).
// Thread = (gt g = tid&63, r = tid>>6) scanning 64 preds in 2 independent
// argmax sub-chains (cross-mult compare, FSEL updates, sticky 1e-6 near-tie
// band resolved by exact-division rescan -> ordering == reference rounded-
// quotient argmax). Threshold/ignore candidates pass ONE coarse in-loop
// filter (inter >= 0.39*den, strict superset of both canonical tests); the
// rare drain re-tests with canonical forms (0.5f/0.4f), so th/ign decisions
// are identical to round 10. Also zero-fills this block's cls slice.
__global__ void __launch_bounds__(256) fused_kernel(const float* __restrict__ gt,
                                                    const float* __restrict__ pr,
                                                    float* __restrict__ out) {
    __shared__ float4 s_pc[256];    // px1, px2, py1, py2
    __shared__ float  s_pa[256];
    __shared__ float  s_W[256], s_cx[256], s_cy[256], s_lw[256], s_lh[256];
    __shared__ int    s_gth[256], s_ign[256];
    __shared__ float  s_lab[GG];
    __shared__ unsigned long long s_key[256];

    int tid = threadIdx.x;
    int b = blockIdx.x >> 7;
    int chunk = blockIdx.x & (NCHUNK - 1);
    int pbase = chunk * 256;

    {   // stage preds
        float4 v = ((const float4*)pr)[pbase + tid];   // pr_boxes[0] per reference
        s_pc[tid] = make_float4(v.x - v.z * 0.5f, v.x + v.z * 0.5f,
                                v.y - v.w * 0.5f, v.y + v.w * 0.5f);
        s_pa[tid] = v.z * v.w;
    }
    s_W[tid] = 0.f; s_cx[tid] = 0.f; s_cy[tid] = 0.f;
    s_lw[tid] = 0.f; s_lh[tid] = 0.f;
    s_gth[tid] = -1; s_ign[tid] = 0;
    if (tid < GG) s_lab[tid] = gt[(b * GG + tid) * 6 + 4];

    {   // zero-fill this block's cls slice; stores drain under compute
        float4* zc = (float4*)out + (size_t)blockIdx.x * 5120;
        float4 z = make_float4(0.f, 0.f, 0.f, 0.f);
#pragma unroll
        for (int i = 0; i < 20; i++) zc[i * 256 + tid] = z;
    }

    int g = tid & 63, r = tid >> 6;
    const float* grow = gt + (b * GG + g) * 6;
    float cx = grow[0], cy = grow[1], gw = grow[2], gh = grow[3];
    bool valid = (cx != -1.0f);
    float gx1 = cx - gw * 0.5f, gx2 = cx + gw * 0.5f;
    float gy1 = cy - gh * 0.5f, gy2 = cy + gh * 0.5f;
    float gaeps = gw * gh + 1e-5f;
    // invalid gt (cx=-1): inverted corners -> iw/ih clamp to 0, inter=0,
    // den>0, so events stay false and the argmax key is gated by 'valid'.
    __syncthreads();

    int base = r * 64;
    float bn0 = 0.f, bd0 = 1.f; int bp0 = base;        // chain 0: preds base+0..31
    float bn1 = 0.f, bd1 = 1.f; int bp1 = base + 32;   // chain 1: preds base+32..63
    unsigned m0 = 0, m1 = 0;
    bool band = false;

#pragma unroll 8
    for (int i = 0; i < 32; i++) {
        unsigned bit = 1u << i;
        {   // chain 0
            float4 c = s_pc[base + i];
            float pa = s_pa[base + i];
            float iw = fmaxf(0.f, fminf(gx2, c.y) - fmaxf(gx1, c.x));
            float ih = fmaxf(0.f, fminf(gy2, c.w) - fmaxf(gy1, c.z));
            float inter = iw * ih;
            float den = (gaeps + pa) - inter;
            float a = inter * bd0, cc = bn0 * den;
            bool acc = a > cc;
            float d = a - cc;
            band = band || ((d != 0.f) && (fabsf(d) <= cc * 1e-6f));
            bn0 = acc ? inter : bn0;
            bd0 = acc ? den : bd0;
            bp0 = acc ? base + i : bp0;
            m0 |= (inter >= 0.39f * den) ? bit : 0u;   // coarse event filter
        }
        {   // chain 1
            float4 c = s_pc[base + 32 + i];
            float pa = s_pa[base + 32 + i];
            float iw = fmaxf(0.f, fminf(gx2, c.y) - fmaxf(gx1, c.x));
            float ih = fmaxf(0.f, fminf(gy2, c.w) - fmaxf(gy1, c.z));
            float inter = iw * ih;
            float den = (gaeps + pa) - inter;
            float a = inter * bd1, cc = bn1 * den;
            bool acc = a > cc;
            float d = a - cc;
            band = band || ((d != 0.f) && (fabsf(d) <= cc * 1e-6f));
            bn1 = acc ? inter : bn1;
            bd1 = acc ? den : bd1;
            bp1 = acc ? base + 32 + i : bp1;
            m1 |= (inter >= 0.39f * den) ? bit : 0u;   // coarse event filter
        }
    }
    {   // merge chains (chain 0 holds lower indices -> keep on tie)
        float a = bn1 * bd0, cc = bn0 * bd1;
        bool acc = a > cc;
        float d = a - cc;
        band = band || ((d != 0.f) && (fabsf(d) <= cc * 1e-6f));
        if (acc) { bn0 = bn1; bd0 = bd1; bp0 = bp1; }
    }
    // near-tie fallback: exact rounded-quotient rescan (essentially never taken)
    if (__any_sync(0xFFFFFFFFu, band)) {
        if (band) {
            float bq = 0.f; int bpx = base;
            for (int i = 0; i < 64; i++) {
                float4 c = s_pc[base + i];
                float pa = s_pa[base + i];
                float iw = fmaxf(0.f, fminf(gx2, c.y) - fmaxf(gx1, c.x));
                float ih = fmaxf(0.f, fminf(gy2, c.w) - fmaxf(gy1, c.z));
                float inter = iw * ih;
                float den = (gaeps + pa) - inter;
                float qq = inter / den;
                if (qq > bq) { bq = qq; bpx = base + i; }
            }
            bn0 = bq; bd0 = 1.f; bp0 = bpx;
        }
    }
    float q = bn0 / bd0;               // one exact div -> reference-rounded key
    s_key[tid] = valid
        ? (((unsigned long long)__float_as_uint(q) << 32) |
           (unsigned)(0xFFFFFFFFu - (unsigned)(pbase + bp0)))
        : 0ULL;

    // drain rare candidate events; re-test with the canonical threshold forms
    unsigned long long evm = ((unsigned long long)m1 << 32) | m0;
    if (!valid) evm = 0ULL;
    if (evm) {
        float lw = logf(gw), lh = logf(gh);
        do {
            int i = __ffsll(evm) - 1; evm &= evm - 1;
            int pp = base + i;
            float4 c = s_pc[pp];
            float pa = s_pa[pp];
            float iw = fmaxf(0.f, fminf(gx2, c.y) - fmaxf(gx1, c.x));
            float ih = fmaxf(0.f, fminf(gy2, c.w) - fmaxf(gy1, c.z));
            float inter = iw * ih;
            float den = (gaeps + pa) - inter;
            if (inter >= 0.5f * den) {              // th (canonical form)
                atomicAdd(&s_W[pp], 1.f);
                atomicAdd(&s_cx[pp], cx);
                atomicAdd(&s_cy[pp], cy);
                atomicAdd(&s_lw[pp], lw);
                atomicAdd(&s_lh[pp], lh);
                atomicMax(&s_gth[pp], g);
            } else if (inter >= 0.4f * den) {       // ignore band (canonical)
                s_ign[pp] = 1;                      // benign race: all store 1
            }
        } while (evm);
    }
    __syncthreads();

    if (tid < GG) {                     // per-(block, gt) argmax partial
        unsigned long long k0 = s_key[tid],       k1 = s_key[tid + 64];
        unsigned long long k2 = s_key[tid + 128], k3 = s_key[tid + 192];
        unsigned long long k = k0 > k1 ? k0 : k1;
        unsigned long long m = k2 > k3 ? k2 : k3;
        k = k > m ? k : m;
        g_partial[(size_t)blockIdx.x * GG + tid] = k;
    }

    // final per-pred outputs (no best-pair term; patch_kernel fixes those)
    {
        float W = s_W[tid];
        int gth = s_gth[tid];
        bool matched = (gth >= 0);
        float mask = matched ? 0.f : 1.f;
        if (s_ign[tid]) mask = -1.f;

        float4 pv = ((const float4*)pr)[pbase + tid];   // L2 hit
        float4 loc;
        if (W > 0.f) {                                   // rare
            loc = make_float4((s_cx[tid] - W * pv.x) / pv.z,
                              (s_cy[tid] - W * pv.y) / pv.w,
                              s_lw[tid] - W * logf(pv.z),
                              s_lh[tid] - W * logf(pv.w));
        } else {
            loc = make_float4(0.f, 0.f, 0.f, 0.f);       // exact when W==0
        }

        size_t idx = (size_t)b * PP + pbase + tid;
        float* out_loc  = out + (size_t)BB * PP * NC;
        float* out_mask = out + (size_t)BB * PP * (NC + 4);
        ((float4*)out_loc)[idx] = loc;
        out_mask[idx] = mask;
        if (matched)                                     // sparse one-hot scatter
            out[idx * NC + (int)s_lab[gth]] = 1.0f;
    }
}

// Kernel A2: reduce 128 chunk-partials -> one key per (b, g). grid 8 x 256.
__global__ void reduce_kernel() {
    __shared__ unsigned long long s_red[256];
    int tid = threadIdx.x;
    int b = blockIdx.x;
    int g = tid & 63, qd = tid >> 6;
    unsigned long long k = 0ULL;
    const unsigned long long* src = g_partial + ((size_t)b * NCHUNK + qd * 32) * GG + g;
#pragma unroll
    for (int i = 0; i < 32; i++) {
        unsigned long long v = src[(size_t)i * GG];
        k = v > k ? v : k;
    }
    s_red[tid] = k;
    __syncthreads();
    if (tid < GG) {
        unsigned long long k0 = s_red[tid],       k1 = s_red[tid + 64];
        unsigned long long k2 = s_red[tid + 128], k3 = s_red[tid + 192];
        unsigned long long a = k0 > k1 ? k0 : k1;
        unsigned long long c = k2 > k3 ? k2 : k3;
        g_final[b * GG + tid] = a > c ? a : c;
    }
}

// Kernel C: sparse patch of the <=48 best preds per batch. grid 8 x 64.
// Thread = gt; the highest-g owner of each best pred recomputes that pred's
// full assignment (bit-identical fp expressions to fused_kernel -> identical
// th/ign booleans), clears the stale cls bit, rewrites loc/mask/cls.
__global__ void patch_kernel(const float* __restrict__ gt,
                             const float* __restrict__ pr,
                             float* __restrict__ out) {
    __shared__ float4 s_box[GG];    // gx1, gx2, gy1, gy2
    __shared__ float4 s_info[GG];   // cx, cy, log(gw), log(gh)
    __shared__ float  s_S[GG];      // ga + 1e-5
    __shared__ float  s_lab[GG];
    __shared__ int    s_bp[GG];

    int g = threadIdx.x;
    int b = blockIdx.x;
    const float* grow = gt + (b * GG + g) * 6;
    float cx = grow[0], cy = grow[1], w = grow[2], h = grow[3];
    bool valid = (cx != -1.0f);
    s_lab[g] = grow[4];
    float conf = grow[5];
    if (valid) {
        s_box[g] = make_float4(cx - w * 0.5f, cx + w * 0.5f,
                               cy - h * 0.5f, cy + h * 0.5f);
        s_info[g] = make_float4(cx, cy, logf(w), logf(h));
        s_S[g] = w * h + 1e-5f;
    } else {
        s_box[g] = make_float4(4.f, 4.f, 4.f, 4.f);   // zero inter with any pred
        s_info[g] = make_float4(0.f, 0.f, 0.f, 0.f);
        s_S[g] = 1e-5f;
    }
    int bp = -1;
    if (valid && conf > 0.f) {
        unsigned long long k = g_final[b * GG + g];
        bp = (int)(0xFFFFFFFFu - (unsigned)(k & 0xFFFFFFFFull));
    }
    s_bp[g] = bp;
    __syncthreads();

    if (bp < 0) return;
    for (int g2 = g + 1; g2 < GG; g2++)
        if (s_bp[g2] == bp) return;      // not the owner (highest g owns)

    float4 pv = ((const float4*)pr)[bp];
    float px1 = pv.x - pv.z * 0.5f, px2 = pv.x + pv.z * 0.5f;
    float py1 = pv.y - pv.w * 0.5f, py2 = pv.y + pv.w * 0.5f;
    float pa = pv.z * pv.w;

    float W = 0.f, Scx = 0.f, Scy = 0.f, Slw = 0.f, Slh = 0.f;
    int gth = -1, gbe = -1;
    bool ign = false;
    for (int g2 = 0; g2 < GG; g2++) {
        float4 bx = s_box[g2];
        float iw = fmaxf(0.f, fminf(bx.y, px2) - fmaxf(bx.x, px1));
        float ih = fmaxf(0.f, fminf(bx.w, py2) - fmaxf(bx.z, py1));
        float inter = iw * ih;
        float den = (s_S[g2] + pa) - inter;    // same fp expr as fused_kernel
        bool th = inter >= 0.5f * den;
        ign = ign || ((inter >= 0.4f * den) && !th);
        bool bst = (s_bp[g2] == bp);
        float wgt = (th ? 1.f : 0.f) + (bst ? 1.f : 0.f);
        if (th) gth = g2;
        if (bst) gbe = g2;
        float4 m = s_info[g2];
        W += wgt;
        Scx += wgt * m.x; Scy += wgt * m.y;
        Slw += wgt * m.z; Slh += wgt * m.w;
    }

    size_t idx = (size_t)b * PP + bp;
    if (gth >= 0)                                 // clear fused's stale cls bit
        out[idx * NC + (int)s_lab[gth]] = 0.f;
    int win = gbe;                                // gbe >= 0 by construction
    out[idx * NC + (int)s_lab[win]] = 1.0f;

    float4 loc = make_float4((Scx - W * pv.x) / pv.z,
                             (Scy - W * pv.y) / pv.w,
                             Slw - W * logf(pv.z),
                             Slh - W * logf(pv.w));
    float mask = ign ? -1.f : 0.f;

    float* out_loc  = out + (size_t)BB * PP * NC;
    float* out_mask = out + (size_t)BB * PP * (NC + 4);
    ((float4*)out_loc)[idx] = loc;
    out_mask[idx] = mask;
}

extern "C" void kernel_launch(void* const* d_in, const int* in_sizes, int n_in,
                              void* d_out, int out_size) {
    const float* gt = (const float*)d_in[0];   // [8,64,6]
    const float* pr = (const float*)d_in[1];   // [8,32768,4]
    float* out = (float*)d_out;                // cls ++ loc ++ mask

    fused_kernel<<<BB * NCHUNK, 256>>>(gt, pr, out);
    reduce_kernel<<<BB, 256>>>();
    patch_kernel<<<BB, GG>>>(gt, pr, out);
}

// round 14
// speedup vs baseline: 1.0710x; 1.0710x over previous
#include <cuda_runtime.h>

#define BB 8
#define GG 64
#define PP 32768
#define NC 80
#define NCHUNK 128           // pred chunks per batch (256 preds each)

// per-(batch, chunk) partial argmax keys: (q_bits << 32) | (0xFFFFFFFF - p)
// all scratch fully overwritten every run -> no init needed, graph-safe.
__device__ unsigned long long g_partial[BB * NCHUNK * GG];
__device__ unsigned long long g_final[BB * GG];
__device__ float4 g_rec[BB * PP * 2];   // per-(b,p): {W,Scx,Scy,Slw},{Slh,gth,ign,0}
__device__ unsigned int g_cnt[BB];      // zero-init; last block resets -> replay-safe

// Kernel A: one pass over all (g, p) pairs of this block's 256 preds.
// Thread = (gt g = tid&63, r = tid>>6) scanning 64 preds in 2 independent
// argmax sub-chains (cross-mult compare, FSEL updates, sticky 1e-6 near-tie
// band resolved by exact-division rescan -> ordering == reference rounded-
// quotient argmax). Threshold/ignore candidates pass ONE coarse in-loop
// filter (inter >= 0.39*den); the rare drain re-tests with canonical forms
// (0.5f/0.4f) -> th/ign decisions identical to round 10. Zero-fills this
// block's cls slice. The LAST block per batch (threadfence-reduction
// pattern) also reduces the 128 chunk partials into g_final in-kernel.
__global__ void __launch_bounds__(256) fused_kernel(const float* __restrict__ gt,
                                                    const float* __restrict__ pr,
                                                    float* __restrict__ out) {
    __shared__ float4 s_pc[256];    // px1, px2, py1, py2
    __shared__ float  s_pa[256];
    __shared__ float  s_W[256], s_cx[256], s_cy[256], s_lw[256], s_lh[256];
    __shared__ int    s_gth[256], s_ign[256];
    __shared__ unsigned long long s_key[256];
    __shared__ unsigned s_last;

    int tid = threadIdx.x;
    int b = blockIdx.x >> 7;
    int chunk = blockIdx.x & (NCHUNK - 1);
    int pbase = chunk * 256;

    {   // stage preds
        float4 v = ((const float4*)pr)[pbase + tid];   // pr_boxes[0] per reference
        s_pc[tid] = make_float4(v.x - v.z * 0.5f, v.x + v.z * 0.5f,
                                v.y - v.w * 0.5f, v.y + v.w * 0.5f);
        s_pa[tid] = v.z * v.w;
    }
    s_W[tid] = 0.f; s_cx[tid] = 0.f; s_cy[tid] = 0.f;
    s_lw[tid] = 0.f; s_lh[tid] = 0.f;
    s_gth[tid] = -1; s_ign[tid] = 0;

    {   // zero-fill this block's cls slice; stores drain under compute
        float4* zc = (float4*)out + (size_t)blockIdx.x * 5120;
        float4 z = make_float4(0.f, 0.f, 0.f, 0.f);
#pragma unroll
        for (int i = 0; i < 20; i++) zc[i * 256 + tid] = z;
    }

    int g = tid & 63, r = tid >> 6;
    const float* grow = gt + (b * GG + g) * 6;
    float cx = grow[0], cy = grow[1], gw = grow[2], gh = grow[3];
    bool valid = (cx != -1.0f);
    float gx1 = cx - gw * 0.5f, gx2 = cx + gw * 0.5f;
    float gy1 = cy - gh * 0.5f, gy2 = cy + gh * 0.5f;
    float gaeps = gw * gh + 1e-5f;
    // invalid gt (cx=-1): inverted corners -> iw/ih clamp to 0, inter=0,
    // den>0, so events stay false and the argmax key is gated by 'valid'.
    __syncthreads();

    int base = r * 64;
    float bn0 = 0.f, bd0 = 1.f; int bp0 = base;        // chain 0: preds base+0..31
    float bn1 = 0.f, bd1 = 1.f; int bp1 = base + 32;   // chain 1: preds base+32..63
    unsigned m0 = 0, m1 = 0;
    bool band = false;

#pragma unroll 8
    for (int i = 0; i < 32; i++) {
        unsigned bit = 1u << i;
        {   // chain 0
            float4 c = s_pc[base + i];
            float pa = s_pa[base + i];
            float iw = fmaxf(0.f, fminf(gx2, c.y) - fmaxf(gx1, c.x));
            float ih = fmaxf(0.f, fminf(gy2, c.w) - fmaxf(gy1, c.z));
            float inter = iw * ih;
            float den = (gaeps + pa) - inter;
            float a = inter * bd0, cc = bn0 * den;
            bool acc = a > cc;
            float d = a - cc;
            band = band || ((d != 0.f) && (fabsf(d) <= cc * 1e-6f));
            bn0 = acc ? inter : bn0;
            bd0 = acc ? den : bd0;
            bp0 = acc ? base + i : bp0;
            m0 |= (inter >= 0.39f * den) ? bit : 0u;   // coarse event filter
        }
        {   // chain 1
            float4 c = s_pc[base + 32 + i];
            float pa = s_pa[base + 32 + i];
            float iw = fmaxf(0.f, fminf(gx2, c.y) - fmaxf(gx1, c.x));
            float ih = fmaxf(0.f, fminf(gy2, c.w) - fmaxf(gy1, c.z));
            float inter = iw * ih;
            float den = (gaeps + pa) - inter;
            float a = inter * bd1, cc = bn1 * den;
            bool acc = a > cc;
            float d = a - cc;
            band = band || ((d != 0.f) && (fabsf(d) <= cc * 1e-6f));
            bn1 = acc ? inter : bn1;
            bd1 = acc ? den : bd1;
            bp1 = acc ? base + 32 + i : bp1;
            m1 |= (inter >= 0.39f * den) ? bit : 0u;   // coarse event filter
        }
    }
    {   // merge chains (chain 0 holds lower indices -> keep on tie)
        float a = bn1 * bd0, cc = bn0 * bd1;
        bool acc = a > cc;
        float d = a - cc;
        band = band || ((d != 0.f) && (fabsf(d) <= cc * 1e-6f));
        if (acc) { bn0 = bn1; bd0 = bd1; bp0 = bp1; }
    }
    // near-tie fallback: exact rounded-quotient rescan (essentially never taken)
    if (__any_sync(0xFFFFFFFFu, band)) {
        if (band) {
            float bq = 0.f; int bpx = base;
            for (int i = 0; i < 64; i++) {
                float4 c = s_pc[base + i];
                float pa = s_pa[base + i];
                float iw = fmaxf(0.f, fminf(gx2, c.y) - fmaxf(gx1, c.x));
                float ih = fmaxf(0.f, fminf(gy2, c.w) - fmaxf(gy1, c.z));
                float inter = iw * ih;
                float den = (gaeps + pa) - inter;
                float qq = inter / den;
                if (qq > bq) { bq = qq; bpx = base + i; }
            }
            bn0 = bq; bd0 = 1.f; bp0 = bpx;
        }
    }
    float q = bn0 / bd0;               // one exact div -> reference-rounded key
    s_key[tid] = valid
        ? (((unsigned long long)__float_as_uint(q) << 32) |
           (unsigned)(0xFFFFFFFFu - (unsigned)(pbase + bp0)))
        : 0ULL;

    // drain rare candidate events; re-test with the canonical threshold forms
    unsigned long long evm = ((unsigned long long)m1 << 32) | m0;
    if (!valid) evm = 0ULL;
    if (evm) {
        float lw = logf(gw), lh = logf(gh);
        do {
            int i = __ffsll(evm) - 1; evm &= evm - 1;
            int pp = base + i;
            float4 c = s_pc[pp];
            float pa = s_pa[pp];
            float iw = fmaxf(0.f, fminf(gx2, c.y) - fmaxf(gx1, c.x));
            float ih = fmaxf(0.f, fminf(gy2, c.w) - fmaxf(gy1, c.z));
            float inter = iw * ih;
            float den = (gaeps + pa) - inter;
            if (inter >= 0.5f * den) {              // th (canonical form)
                atomicAdd(&s_W[pp], 1.f);
                atomicAdd(&s_cx[pp], cx);
                atomicAdd(&s_cy[pp], cy);
                atomicAdd(&s_lw[pp], lw);
                atomicAdd(&s_lh[pp], lh);
                atomicMax(&s_gth[pp], g);
            } else if (inter >= 0.4f * den) {       // ignore band (canonical)
                s_ign[pp] = 1;                      // benign race: all store 1
            }
        } while (evm);
    }
    __syncthreads();

    if (tid < GG) {                     // per-(block, gt) argmax partial
        unsigned long long k0 = s_key[tid],       k1 = s_key[tid + 64];
        unsigned long long k2 = s_key[tid + 128], k3 = s_key[tid + 192];
        unsigned long long k = k0 > k1 ? k0 : k1;
        unsigned long long m = k2 > k3 ? k2 : k3;
        k = k > m ? k : m;
        g_partial[(size_t)blockIdx.x * GG + tid] = k;
    }

    size_t idx = (size_t)b * PP + pbase + tid;      // per-pred record
    g_rec[idx * 2]     = make_float4(s_W[tid], s_cx[tid], s_cy[tid], s_lw[tid]);
    g_rec[idx * 2 + 1] = make_float4(s_lh[tid], __int_as_float(s_gth[tid]),
                                     __int_as_float(s_ign[tid]), 0.f);

    // ---- threadfence-reduction: last block of this batch reduces partials ----
    __threadfence();                    // order g_partial stores before counter
    __syncthreads();                    // also: everyone done reading s_key
    if (tid == 0) {
        unsigned v = atomicAdd(&g_cnt[b], 1u);
        s_last = (v == NCHUNK - 1) ? 1u : 0u;
        if (v == NCHUNK - 1) g_cnt[b] = 0;          // reset -> graph-replay-safe
    }
    __syncthreads();
    if (s_last) {
        int gg = tid & 63, qd = tid >> 6;
        unsigned long long k = 0ULL;
        const unsigned long long* src =
            g_partial + ((size_t)b * NCHUNK + qd * 32) * GG + gg;
#pragma unroll
        for (int i = 0; i < 32; i++) {
            unsigned long long v = src[(size_t)i * GG];
            k = v > k ? v : k;
        }
        s_key[tid] = k;
        __syncthreads();
        if (tid < GG) {
            unsigned long long k0 = s_key[tid],       k1 = s_key[tid + 64];
            unsigned long long k2 = s_key[tid + 128], k3 = s_key[tid + 192];
            unsigned long long a = k0 > k1 ? k0 : k1;
            unsigned long long c = k2 > k3 ? k2 : k3;
            g_final[b * GG + tid] = a > c ? a : c;
        }
    }
}

// Kernel B: merge best-pair term + finalize. No per-gt loop. grid (128, 8).
__global__ void __launch_bounds__(256) finalize_kernel(const float* __restrict__ gt,
                                                       const float* __restrict__ pr,
                                                       float* __restrict__ out) {
    __shared__ float s_bw[256], s_bx[256], s_by[256], s_blw[256], s_blh[256];
    __shared__ int   s_bg[256];
    __shared__ float s_lab[GG];

    int tid = threadIdx.x;
    int b = blockIdx.y;

    s_bw[tid] = 0.f; s_bx[tid] = 0.f; s_by[tid] = 0.f;
    s_blw[tid] = 0.f; s_blh[tid] = 0.f; s_bg[tid] = -1;

    if (tid < GG) {
        const float* grow = gt + (b * GG + tid) * 6;
        float cx = grow[0];
        s_lab[tid] = grow[4];
        bool valid = (cx != -1.0f);
        float conf = grow[5];
        if (valid && conf > 0.f) {
            unsigned long long k = g_final[b * GG + tid];
            int bp = (int)(0xFFFFFFFFu - (unsigned)(k & 0xFFFFFFFFull));
            if ((bp >> 8) == (int)blockIdx.x) {     // best pred lives in this block
                int lp = bp & 255;
                atomicAdd(&s_bw[lp], 1.f);
                atomicAdd(&s_bx[lp], cx);
                atomicAdd(&s_by[lp], grow[1]);
                atomicAdd(&s_blw[lp], logf(grow[2]));
                atomicAdd(&s_blh[lp], logf(grow[3]));
                atomicMax(&s_bg[lp], tid);          // original gt index (monotone)
            }
        }
    }
    __syncthreads();

    int p = blockIdx.x * 256 + tid;
    size_t idx = (size_t)b * PP + p;
    float4 r0 = g_rec[idx * 2];
    float4 r1 = g_rec[idx * 2 + 1];

    float W   = r0.x + s_bw[tid];
    float Scx = r0.y + s_bx[tid];
    float Scy = r0.z + s_by[tid];
    float Slw = r0.w + s_blw[tid];
    float Slh = r1.x + s_blh[tid];
    int gth = __float_as_int(r1.y);
    bool ign = __float_as_int(r1.z) != 0;
    int gbe = s_bg[tid];

    int win = (gbe >= 0) ? gbe : gth;
    bool matched = (win >= 0);
    float mask = matched ? 0.f : 1.f;
    if (ign) mask = -1.f;

    float4 pv = ((const float4*)pr)[p];
    float4 loc;
    if (W > 0.f) {
        loc = make_float4((Scx - W * pv.x) / pv.z,
                          (Scy - W * pv.y) / pv.w,
                          Slw - W * logf(pv.z),
                          Slh - W * logf(pv.w));
    } else {
        loc = make_float4(0.f, 0.f, 0.f, 0.f);      // exact: sums are 0 when W==0
    }

    float* out_loc  = out + (size_t)BB * PP * NC;
    float* out_mask = out + (size_t)BB * PP * (NC + 4);
    ((float4*)out_loc)[idx] = loc;
    out_mask[idx] = mask;

    if (matched) {                                  // sparse one-hot scatter
        int cid = (int)s_lab[win];
        out[idx * NC + cid] = 1.0f;
    }
}

extern "C" void kernel_launch(void* const* d_in, const int* in_sizes, int n_in,
                              void* d_out, int out_size) {
    const float* gt = (const float*)d_in[0];   // [8,64,6]
    const float* pr = (const float*)d_in[1];   // [8,32768,4]
    float* out = (float*)d_out;                // cls ++ loc ++ mask

    fused_kernel<<<BB * NCHUNK, 256>>>(gt, pr, out);
    dim3 gridB(PP / 256, BB);
    finalize_kernel<<<gridB, 256>>>(gt, pr, out);
}

// round 15
// speedup vs baseline: 1.0952x; 1.0226x over previous
#include <cuda_runtime.h>

#define BB 8
#define GG 64
#define PP 32768
#define NC 80
#define NCHUNK 128           // pred chunks per batch (256 preds each)

// per-(batch, chunk) partial argmax keys: (q_bits << 32) | (0xFFFFFFFF - p)
// all scratch fully overwritten every run -> no init needed, graph-safe.
__device__ unsigned long long g_partial[BB * NCHUNK * GG];
__device__ unsigned long long g_final[BB * GG];
__device__ float4 g_rec[BB * PP * 2];   // per-(b,p): {W,Scx,Scy,Slw},{Slh,gth,ign,0}

// Kernel A: one pass over all (g, p) pairs of this block's 256 preds.
// Thread = (gt g = tid&63, r = tid>>6) scanning 64 preds in 2 independent
// argmax sub-chains (cross-mult compare, FSEL updates, sticky 1e-6 near-tie
// band resolved by exact-division rescan -> ordering == reference rounded-
// quotient argmax). Threshold/ignore candidates pass ONE coarse in-loop
// filter (inter >= 0.39*den); the rare drain re-tests with canonical forms
// (0.5f/0.4f). cls zero-fill uses streaming stores (__stcs) so the 84MB
// stream does not evict g_rec/pr from L2 before finalize reads them.
__global__ void __launch_bounds__(256) fused_kernel(const float* __restrict__ gt,
                                                    const float* __restrict__ pr,
                                                    float* __restrict__ out) {
    __shared__ float4 s_pc[256];    // px1, px2, py1, py2
    __shared__ float  s_pa[256];
    __shared__ float  s_W[256], s_cx[256], s_cy[256], s_lw[256], s_lh[256];
    __shared__ int    s_gth[256], s_ign[256];
    __shared__ unsigned long long s_key[256];

    int tid = threadIdx.x;
    int b = blockIdx.x >> 7;
    int chunk = blockIdx.x & (NCHUNK - 1);
    int pbase = chunk * 256;

    {   // stage preds
        float4 v = ((const float4*)pr)[pbase + tid];   // pr_boxes[0] per reference
        s_pc[tid] = make_float4(v.x - v.z * 0.5f, v.x + v.z * 0.5f,
                                v.y - v.w * 0.5f, v.y + v.w * 0.5f);
        s_pa[tid] = v.z * v.w;
    }
    s_W[tid] = 0.f; s_cx[tid] = 0.f; s_cy[tid] = 0.f;
    s_lw[tid] = 0.f; s_lh[tid] = 0.f;
    s_gth[tid] = -1; s_ign[tid] = 0;

    {   // zero-fill this block's cls slice with STREAMING stores (evict-first)
        float4* zc = (float4*)out + (size_t)blockIdx.x * 5120;
        float4 z = make_float4(0.f, 0.f, 0.f, 0.f);
#pragma unroll
        for (int i = 0; i < 20; i++) __stcs(&zc[i * 256 + tid], z);
    }

    int g = tid & 63, r = tid >> 6;
    const float* grow = gt + (b * GG + g) * 6;
    float cx = grow[0], cy = grow[1], gw = grow[2], gh = grow[3];
    bool valid = (cx != -1.0f);
    float gx1 = cx - gw * 0.5f, gx2 = cx + gw * 0.5f;
    float gy1 = cy - gh * 0.5f, gy2 = cy + gh * 0.5f;
    float gaeps = gw * gh + 1e-5f;
    // invalid gt (cx=-1): inverted corners -> iw/ih clamp to 0, inter=0,
    // den>0, so events stay false and the argmax key is gated by 'valid'.
    __syncthreads();

    int base = r * 64;
    float bn0 = 0.f, bd0 = 1.f; int bp0 = base;        // chain 0: preds base+0..31
    float bn1 = 0.f, bd1 = 1.f; int bp1 = base + 32;   // chain 1: preds base+32..63
    unsigned m0 = 0, m1 = 0;
    bool band = false;

#pragma unroll 8
    for (int i = 0; i < 32; i++) {
        unsigned bit = 1u << i;
        {   // chain 0
            float4 c = s_pc[base + i];
            float pa = s_pa[base + i];
            float iw = fmaxf(0.f, fminf(gx2, c.y) - fmaxf(gx1, c.x));
            float ih = fmaxf(0.f, fminf(gy2, c.w) - fmaxf(gy1, c.z));
            float inter = iw * ih;
            float den = (gaeps + pa) - inter;
            float a = inter * bd0, cc = bn0 * den;
            bool acc = a > cc;
            float d = a - cc;
            band = band || ((d != 0.f) && (fabsf(d) <= cc * 1e-6f));
            bn0 = acc ? inter : bn0;
            bd0 = acc ? den : bd0;
            bp0 = acc ? base + i : bp0;
            m0 |= (inter >= 0.39f * den) ? bit : 0u;   // coarse event filter
        }
        {   // chain 1
            float4 c = s_pc[base + 32 + i];
            float pa = s_pa[base + 32 + i];
            float iw = fmaxf(0.f, fminf(gx2, c.y) - fmaxf(gx1, c.x));
            float ih = fmaxf(0.f, fminf(gy2, c.w) - fmaxf(gy1, c.z));
            float inter = iw * ih;
            float den = (gaeps + pa) - inter;
            float a = inter * bd1, cc = bn1 * den;
            bool acc = a > cc;
            float d = a - cc;
            band = band || ((d != 0.f) && (fabsf(d) <= cc * 1e-6f));
            bn1 = acc ? inter : bn1;
            bd1 = acc ? den : bd1;
            bp1 = acc ? base + 32 + i : bp1;
            m1 |= (inter >= 0.39f * den) ? bit : 0u;   // coarse event filter
        }
    }
    {   // merge chains (chain 0 holds lower indices -> keep on tie)
        float a = bn1 * bd0, cc = bn0 * bd1;
        bool acc = a > cc;
        float d = a - cc;
        band = band || ((d != 0.f) && (fabsf(d) <= cc * 1e-6f));
        if (acc) { bn0 = bn1; bd0 = bd1; bp0 = bp1; }
    }
    // near-tie fallback: exact rounded-quotient rescan (essentially never taken)
    if (__any_sync(0xFFFFFFFFu, band)) {
        if (band) {
            float bq = 0.f; int bpx = base;
            for (int i = 0; i < 64; i++) {
                float4 c = s_pc[base + i];
                float pa = s_pa[base + i];
                float iw = fmaxf(0.f, fminf(gx2, c.y) - fmaxf(gx1, c.x));
                float ih = fmaxf(0.f, fminf(gy2, c.w) - fmaxf(gy1, c.z));
                float inter = iw * ih;
                float den = (gaeps + pa) - inter;
                float qq = inter / den;
                if (qq > bq) { bq = qq; bpx = base + i; }
            }
            bn0 = bq; bd0 = 1.f; bp0 = bpx;
        }
    }
    float q = bn0 / bd0;               // one exact div -> reference-rounded key
    s_key[tid] = valid
        ? (((unsigned long long)__float_as_uint(q) << 32) |
           (unsigned)(0xFFFFFFFFu - (unsigned)(pbase + bp0)))
        : 0ULL;

    // drain rare candidate events; re-test with the canonical threshold forms
    unsigned long long evm = ((unsigned long long)m1 << 32) | m0;
    if (!valid) evm = 0ULL;
    if (evm) {
        float lw = logf(gw), lh = logf(gh);
        do {
            int i = __ffsll(evm) - 1; evm &= evm - 1;
            int pp = base + i;
            float4 c = s_pc[pp];
            float pa = s_pa[pp];
            float iw = fmaxf(0.f, fminf(gx2, c.y) - fmaxf(gx1, c.x));
            float ih = fmaxf(0.f, fminf(gy2, c.w) - fmaxf(gy1, c.z));
            float inter = iw * ih;
            float den = (gaeps + pa) - inter;
            if (inter >= 0.5f * den) {              // th (canonical form)
                atomicAdd(&s_W[pp], 1.f);
                atomicAdd(&s_cx[pp], cx);
                atomicAdd(&s_cy[pp], cy);
                atomicAdd(&s_lw[pp], lw);
                atomicAdd(&s_lh[pp], lh);
                atomicMax(&s_gth[pp], g);
            } else if (inter >= 0.4f * den) {       // ignore band (canonical)
                s_ign[pp] = 1;                      // benign race: all store 1
            }
        } while (evm);
    }
    __syncthreads();

    if (tid < GG) {                     // per-(block, gt) argmax partial
        unsigned long long k0 = s_key[tid],       k1 = s_key[tid + 64];
        unsigned long long k2 = s_key[tid + 128], k3 = s_key[tid + 192];
        unsigned long long k = k0 > k1 ? k0 : k1;
        unsigned long long m = k2 > k3 ? k2 : k3;
        k = k > m ? k : m;
        g_partial[(size_t)blockIdx.x * GG + tid] = k;
    }

    size_t idx = (size_t)b * PP + pbase + tid;      // per-pred record
    g_rec[idx * 2]     = make_float4(s_W[tid], s_cx[tid], s_cy[tid], s_lw[tid]);
    g_rec[idx * 2 + 1] = make_float4(s_lh[tid], __int_as_float(s_gth[tid]),
                                     __int_as_float(s_ign[tid]), 0.f);
}

// Kernel A2: reduce 128 chunk-partials -> one key per (b, g). grid 8 x 256.
__global__ void reduce_kernel() {
    __shared__ unsigned long long s_red[256];
    int tid = threadIdx.x;
    int b = blockIdx.x;
    int g = tid & 63, qd = tid >> 6;
    unsigned long long k = 0ULL;
    const unsigned long long* src = g_partial + ((size_t)b * NCHUNK + qd * 32) * GG + g;
#pragma unroll
    for (int i = 0; i < 32; i++) {
        unsigned long long v = src[(size_t)i * GG];
        k = v > k ? v : k;
    }
    s_red[tid] = k;
    __syncthreads();
    if (tid < GG) {
        unsigned long long k0 = s_red[tid],       k1 = s_red[tid + 64];
        unsigned long long k2 = s_red[tid + 128], k3 = s_red[tid + 192];
        unsigned long long a = k0 > k1 ? k0 : k1;
        unsigned long long c = k2 > k3 ? k2 : k3;
        g_final[b * GG + tid] = a > c ? a : c;
    }
}

// Kernel B: merge best-pair term + finalize. grid (128, 8).
// g_rec / pr loads are issued at kernel entry (before staging + barrier) so
// their latency is covered by the staging phase; __ldcs = read-once hint.
__global__ void __launch_bounds__(256) finalize_kernel(const float* __restrict__ gt,
                                                       const float* __restrict__ pr,
                                                       float* __restrict__ out) {
    __shared__ float s_bw[256], s_bx[256], s_by[256], s_blw[256], s_blh[256];
    __shared__ int   s_bg[256];
    __shared__ float s_lab[GG];

    int tid = threadIdx.x;
    int b = blockIdx.y;
    int p = blockIdx.x * 256 + tid;
    size_t idx = (size_t)b * PP + p;

    // issue long-latency loads FIRST; consumed after the staging barrier
    float4 r0 = __ldcs(&g_rec[idx * 2]);
    float4 r1 = __ldcs(&g_rec[idx * 2 + 1]);
    float4 pv = ((const float4*)pr)[p];

    s_bw[tid] = 0.f; s_bx[tid] = 0.f; s_by[tid] = 0.f;
    s_blw[tid] = 0.f; s_blh[tid] = 0.f; s_bg[tid] = -1;

    if (tid < GG) {
        const float* grow = gt + (b * GG + tid) * 6;
        float cx = grow[0];
        s_lab[tid] = grow[4];
        bool valid = (cx != -1.0f);
        float conf = grow[5];
        if (valid && conf > 0.f) {
            unsigned long long k = g_final[b * GG + tid];
            int bp = (int)(0xFFFFFFFFu - (unsigned)(k & 0xFFFFFFFFull));
            if ((bp >> 8) == (int)blockIdx.x) {     // best pred lives in this block
                int lp = bp & 255;
                atomicAdd(&s_bw[lp], 1.f);
                atomicAdd(&s_bx[lp], cx);
                atomicAdd(&s_by[lp], grow[1]);
                atomicAdd(&s_blw[lp], logf(grow[2]));
                atomicAdd(&s_blh[lp], logf(grow[3]));
                atomicMax(&s_bg[lp], tid);          // original gt index (monotone)
            }
        }
    }
    __syncthreads();

    float W   = r0.x + s_bw[tid];
    float Scx = r0.y + s_bx[tid];
    float Scy = r0.z + s_by[tid];
    float Slw = r0.w + s_blw[tid];
    float Slh = r1.x + s_blh[tid];
    int gth = __float_as_int(r1.y);
    bool ign = __float_as_int(r1.z) != 0;
    int gbe = s_bg[tid];

    int win = (gbe >= 0) ? gbe : gth;
    bool matched = (win >= 0);
    float mask = matched ? 0.f : 1.f;
    if (ign) mask = -1.f;

    float4 loc;
    if (W > 0.f) {
        loc = make_float4((Scx - W * pv.x) / pv.z,
                          (Scy - W * pv.y) / pv.w,
                          Slw - W * logf(pv.z),
                          Slh - W * logf(pv.w));
    } else {
        loc = make_float4(0.f, 0.f, 0.f, 0.f);      // exact: sums are 0 when W==0
    }

    float* out_loc  = out + (size_t)BB * PP * NC;
    float* out_mask = out + (size_t)BB * PP * (NC + 4);
    ((float4*)out_loc)[idx] = loc;
    out_mask[idx] = mask;

    if (matched) {                                  // sparse one-hot scatter
        int cid = (int)s_lab[win];
        out[idx * NC + cid] = 1.0f;
    }
}

extern "C" void kernel_launch(void* const* d_in, const int* in_sizes, int n_in,
                              void* d_out, int out_size) {
    const float* gt = (const float*)d_in[0];   // [8,64,6]
    const float* pr = (const float*)d_in[1];   // [8,32768,4]
    float* out = (float*)d_out;                // cls ++ loc ++ mask

    fused_kernel<<<BB * NCHUNK, 256>>>(gt, pr, out);
    reduce_kernel<<<BB, 256>>>();
    dim3 gridB(PP / 256, BB);
    finalize_kernel<<<gridB, 256>>>(gt, pr, out);
}